// round 12
// baseline (speedup 1.0000x reference)
#include <cuda_runtime.h>
#include <cuda_bf16.h>

// ---------------------------------------------------------------------------
// GaussianVoxelizer, single fused kernel (regular-grid path):
//   grid = 8x8x4-voxel tiles (13x13x2 = 338 blocks), 512 threads:
//   2 threads per voxel (survivor-segment halves) -> 8 warps/SMSP of
//   latency hiding WITHOUT duplicating the per-block cull scan (R11 lesson).
//   Per block:
//     - analytic tile AABB from blockIdx (regular grid),
//     - 5-sigma per-axis cull (+ reference's exact 3-sigma vol mask),
//       loads + inversion hoisted before the ballot (full MLP),
//       16-warp warp-private compaction (SEG=64) into pair-interleaved recs,
//     - eval: half 0 = segments 0-7, half 1 = segments 8-15, packed f32x2
//       2-pair pipeline with dual accumulators,
//     - intra-block combine in fixed order (deterministic, no atomics).
//   Cull safety: maha >= d_i^2/Sigma_ii => culled weight < exp(-12.5)~3.7e-6.
// Fallback (non-regular grid): brute force, correctness only.
// ---------------------------------------------------------------------------

#define GCHUNK 1024
#define NWARP  16
#define SEG    (GCHUNK / NWARP)   // gaussians per warp segment (64)
#define SEGP   (SEG / 2)          // pairs per warp segment (32)
#define TSX 8
#define TSY 8
#define TSZ 4
#define CULL_K 5.0f

__device__ __forceinline__ float ex2_approx(float x) {
    float y;
    asm("ex2.approx.ftz.f32 %0, %1;" : "=f"(y) : "f"(x));
    return y;
}
__device__ __forceinline__ unsigned long long pack_x2(float lo, float hi) {
    unsigned long long r;
    asm("mov.b64 %0, {%1, %2};" : "=l"(r) : "f"(lo), "f"(hi));
    return r;
}
__device__ __forceinline__ void unpack_x2(unsigned long long v, float& lo, float& hi) {
    asm("mov.b64 {%0, %1}, %2;" : "=f"(lo), "=f"(hi) : "l"(v));
}
__device__ __forceinline__ unsigned long long add_x2(unsigned long long a, unsigned long long b) {
    unsigned long long d;
    asm("add.rn.f32x2 %0, %1, %2;" : "=l"(d) : "l"(a), "l"(b));
    return d;
}
__device__ __forceinline__ unsigned long long mul_x2(unsigned long long a, unsigned long long b) {
    unsigned long long d;
    asm("mul.rn.f32x2 %0, %1, %2;" : "=l"(d) : "l"(a), "l"(b));
    return d;
}
__device__ __forceinline__ unsigned long long fma_x2(unsigned long long a, unsigned long long b,
                                                     unsigned long long c) {
    unsigned long long d;
    asm("fma.rn.f32x2 %0, %1, %2, %3;" : "=l"(d) : "l"(a), "l"(b), "l"(c));
    return d;
}

__device__ __forceinline__ void eval_pair(
    const ulonglong2 r0, const ulonglong2 r1, const ulonglong2 r2,
    const ulonglong2 r3, const ulonglong2 r4,
    unsigned long long cxx, unsigned long long cyy, unsigned long long czz,
    float& acc) {
    unsigned long long dx = add_x2(cxx, r0.x);
    unsigned long long dy = add_x2(cyy, r0.y);
    unsigned long long dz = add_x2(czz, r1.x);
    unsigned long long t0 = fma_x2(r2.x, dx, fma_x2(r2.y, dy, mul_x2(r3.x, dz)));
    unsigned long long t1 = fma_x2(r3.y, dy, mul_x2(r4.x, dz));
    unsigned long long t2 = mul_x2(mul_x2(r4.y, dz), dz);
    unsigned long long ee = fma_x2(dx, t0, fma_x2(dy, t1, t2));
    float e0, e1, op0, op1;
    unpack_x2(ee, e0, e1);
    unpack_x2(r1.y, op0, op1);
    acc = fmaf(op0, ex2_approx(e0), acc);
    acc = fmaf(op1, ex2_approx(e1), acc);
}

__global__ __launch_bounds__(512, 2) void gv_tile(
    const float* __restrict__ means,
    const float* __restrict__ ops,
    const float* __restrict__ covs,
    const float* __restrict__ vr,
    float* __restrict__ out,
    int G, int NX, int NY, int NZ) {
    // Pair-interleaved survivor records: pair slot = 5 x ulonglong2 (80B).
    __shared__ ulonglong2 s_rec[(GCHUNK / 2) * 5];   // 40 KB
    __shared__ float s_red[TSX * TSY * TSZ];         // combine buffer (1 KB)
    __shared__ int s_cnt[NWARP];

    const int tid = threadIdx.x;
    const int lane = tid & 31;
    const int wid = tid >> 5;
    const int vox = tid & 255;      // voxel within tile
    const int half = tid >> 8;      // survivor-segment half

    const float v0 = vr[0], v1 = vr[1], v2 = vr[2];
    const float v3 = vr[3], v4 = vr[4], v5 = vr[5];
    const float voxx = (v3 - v0) / (float)NX;
    const float voxy = (v4 - v1) / (float)NY;
    const float voxz = (v5 - v2) / (float)NZ;

    // ---- analytic tile AABB (voxel centers, clamped) ----
    const int x0 = blockIdx.x * TSX, x1 = min(x0 + TSX - 1, NX - 1);
    const int y0 = blockIdx.y * TSY, y1 = min(y0 + TSY - 1, NY - 1);
    const int z0 = blockIdx.z * TSZ, z1 = min(z0 + TSZ - 1, NZ - 1);
    const float lox = v0 + ((float)x0 + 0.5f) * voxx;
    const float hix = v0 + ((float)x1 + 0.5f) * voxx;
    const float loy = v1 + ((float)y0 + 0.5f) * voxy;
    const float hiy = v1 + ((float)y1 + 0.5f) * voxy;
    const float loz = v2 + ((float)z0 + 0.5f) * voxz;
    const float hiz = v2 + ((float)z1 + 0.5f) * voxz;

    // ---- this thread's voxel (vox: x = bits[5:8), y = bits[2:5), z = bits[0:2)) ----
    const int X = x0 + (vox >> 5);
    const int Y = y0 + ((vox >> 2) & 7);
    const int Z = z0 + (vox & 3);
    const bool valid = (X < NX) && (Y < NY) && (Z < NZ);
    const float cx = v0 + ((float)X + 0.5f) * voxx;
    const float cy = v1 + ((float)Y + 0.5f) * voxy;
    const float cz = v2 + ((float)Z + 0.5f) * voxz;
    const unsigned long long cxx = pack_x2(cx, cx);
    const unsigned long long cyy = pack_x2(cy, cy);
    const unsigned long long czz = pack_x2(cz, cz);

    float acc0 = 0.0f, acc1 = 0.0f;
    float* frec = (float*)s_rec;

    for (int gbase = 0; gbase < G; gbase += GCHUNK) {
        const int chunk = min(GCHUNK, G - gbase);

        // ---- warp-private cull + pair-interleaved compaction (16 warps) ----
        const int wbase = wid * SEG;
        int wcount = 0;
#pragma unroll
        for (int p = 0; p < SEG; p += 32) {
            const int rel = wbase + p + lane;
            const bool inb = rel < chunk;
            const int g = gbase + (inb ? rel : 0);

            // unconditional clamped loads -> full MLP batch
            float mx  = means[3 * g + 0];
            float my  = means[3 * g + 1];
            float mz  = means[3 * g + 2];
            float op  = ops[g];
            float caa = covs[9 * g + 0];
            float cab = covs[9 * g + 1];
            float cac = covs[9 * g + 2];
            float cbb = covs[9 * g + 4];
            float cbc = covs[9 * g + 5];
            float ccc = covs[9 * g + 8];

            float sqa = sqrtf(caa), sqb = sqrtf(cbb), sqc = sqrtf(ccc);
            // reference's 3-sigma volume-range mask (exact form)
            bool mask = (mx + 3.0f * sqa > v0) && (my + 3.0f * sqb > v1) &&
                        (mz + 3.0f * sqc > v2) && (mx - 3.0f * sqa < v3) &&
                        (my - 3.0f * sqb < v4) && (mz - 3.0f * sqc < v5);
            // 5-sigma per-axis tile cull
            float gx = fmaxf(fmaxf(lox - mx, mx - hix), 0.0f);
            float gy = fmaxf(fmaxf(loy - my, my - hiy), 0.0f);
            float gz = fmaxf(fmaxf(loz - mz, mz - hiz), 0.0f);
            bool survive = inb && mask && (op != 0.0f) &&
                           (gx <= CULL_K * sqa) && (gy <= CULL_K * sqb) &&
                           (gz <= CULL_K * sqc);

            // inversion hoisted (cheap math; wasted for dead lanes)
            float C00 = cbb * ccc - cbc * cbc;
            float C01 = cac * cbc - cab * ccc;
            float C02 = cab * cbc - cac * cbb;
            float C11 = caa * ccc - cac * cac;
            float C12 = cab * cac - caa * cbc;
            float C22 = caa * cbb - cab * cab;
            float det = caa * C00 + cab * C01 + cac * C02;
            float s = -0.72134752044448170f / det;

            unsigned m = __ballot_sync(0xffffffffu, survive);
            if (survive) {
                const int pos = wbase + wcount + __popc(m & ((1u << lane) - 1u));
                float* f = frec + 20 * (pos >> 1) + (pos & 1);
                f[0]  = -mx;
                f[2]  = -my;
                f[4]  = -mz;
                f[6]  = op;
                f[8]  = s * C00;
                f[10] = 2.0f * s * C01;
                f[12] = 2.0f * s * C02;
                f[14] = s * C11;
                f[16] = 2.0f * s * C12;
                f[18] = s * C22;
            }
            wcount += __popc(m);
        }
        // pad odd count with a zero record (op=0, q=0 -> contributes exactly 0)
        if ((wcount & 1) && lane == 0) {
            float* f = frec + 20 * ((wbase + wcount) >> 1) + 1;
#pragma unroll
            for (int fi = 0; fi < 10; ++fi) f[2 * fi] = 0.0f;
        }
        if (lane == 0) s_cnt[wid] = wcount;
        __syncthreads();

        // ---- evaluate survivor pairs: this half's 8 segments ----
#pragma unroll
        for (int w8 = 0; w8 < 8; ++w8) {
            const int w = half * 8 + w8;
            const int np = (s_cnt[w] + 1) >> 1;
            const int pb = w * SEGP;
            int i = 0;
            for (; i + 2 <= np; i += 2) {
                const ulonglong2* Ra = &s_rec[5 * (pb + i)];
                const ulonglong2* Rb = &s_rec[5 * (pb + i + 1)];
                ulonglong2 a0 = Ra[0], a1 = Ra[1], a2 = Ra[2], a3 = Ra[3], a4 = Ra[4];
                ulonglong2 b0 = Rb[0], b1 = Rb[1], b2 = Rb[2], b3 = Rb[3], b4 = Rb[4];
                eval_pair(a0, a1, a2, a3, a4, cxx, cyy, czz, acc0);
                eval_pair(b0, b1, b2, b3, b4, cxx, cyy, czz, acc1);
            }
            if (i < np) {
                const ulonglong2* Ra = &s_rec[5 * (pb + i)];
                eval_pair(Ra[0], Ra[1], Ra[2], Ra[3], Ra[4], cxx, cyy, czz, acc0);
            }
        }
        __syncthreads();
    }

    // ---- intra-block combine, fixed order (deterministic) ----
    if (half == 1) s_red[vox] = acc0 + acc1;
    __syncthreads();
    if (half == 0 && valid)
        out[(X * NY + Y) * NZ + Z] = (acc0 + acc1) + s_red[vox];
}

// Generic fallback: brute force over all gaussians per voxel (any layout).
__global__ __launch_bounds__(256) void gv_brute(
    const float* __restrict__ means,
    const float* __restrict__ ops,
    const float* __restrict__ covs,
    const float* __restrict__ coords,
    const float* __restrict__ vr,
    float* __restrict__ out,
    int G, int N) {
    __shared__ float4 s_a[GCHUNK];
    __shared__ float4 s_b[GCHUNK];
    __shared__ float2 s_c[GCHUNK];
    const int tid = threadIdx.x;
    const float v0 = vr[0], v1 = vr[1], v2 = vr[2];
    const float v3 = vr[3], v4 = vr[4], v5 = vr[5];
    int vidx = blockIdx.x * 256 + tid;
    bool valid = vidx < N;
    int li = valid ? vidx : 0;
    float cx = coords[3 * li + 0];
    float cy = coords[3 * li + 1];
    float cz = coords[3 * li + 2];
    float acc = 0.0f;
    for (int base = 0; base < G; base += GCHUNK) {
        int c = min(GCHUNK, G - base);
        for (int i = tid; i < c; i += 256) {
            int g = base + i;
            float mx = means[3 * g + 0];
            float my = means[3 * g + 1];
            float mz = means[3 * g + 2];
            float op = ops[g];
            float caa = covs[9 * g + 0];
            float cab = covs[9 * g + 1];
            float cac = covs[9 * g + 2];
            float cbb = covs[9 * g + 4];
            float cbc = covs[9 * g + 5];
            float ccc = covs[9 * g + 8];
            float sqa = sqrtf(caa), sqb = sqrtf(cbb), sqc = sqrtf(ccc);
            bool mask = (mx + 3.0f * sqa > v0) && (my + 3.0f * sqb > v1) &&
                        (mz + 3.0f * sqc > v2) && (mx - 3.0f * sqa < v3) &&
                        (my - 3.0f * sqb < v4) && (mz - 3.0f * sqc < v5);
            if (!mask) op = 0.0f;
            float C00 = cbb * ccc - cbc * cbc;
            float C01 = cac * cbc - cab * ccc;
            float C02 = cab * cbc - cac * cbb;
            float C11 = caa * ccc - cac * cac;
            float C12 = cab * cac - caa * cbc;
            float C22 = caa * cbb - cab * cab;
            float det = caa * C00 + cab * C01 + cac * C02;
            float s = -0.72134752044448170f / det;
            s_a[i] = make_float4(-mx, -my, -mz, op);
            s_b[i] = make_float4(s * C00, 2.0f * s * C01, 2.0f * s * C02,
                                 s * C11);
            s_c[i] = make_float2(2.0f * s * C12, s * C22);
        }
        __syncthreads();
        for (int i = 0; i < c; ++i) {
            float4 A = s_a[i];
            float4 B = s_b[i];
            float2 C = s_c[i];
            float dx = cx + A.x;
            float dy = cy + A.y;
            float dz = cz + A.z;
            float t0 = fmaf(B.x, dx, fmaf(B.y, dy, B.z * dz));
            float t1 = fmaf(B.w, dy, C.x * dz);
            float ee = fmaf(dx, t0, fmaf(dy, t1, (C.y * dz) * dz));
            acc = fmaf(A.w, ex2_approx(ee), acc);
        }
        __syncthreads();
    }
    if (valid) out[vidx] = acc;
}

extern "C" void kernel_launch(void* const* d_in, const int* in_sizes, int n_in,
                              void* d_out, int out_size) {
    const float* means  = (const float*)d_in[0];
    const float* ops    = (const float*)d_in[1];
    const float* covs   = (const float*)d_in[2];
    const float* coords = (const float*)d_in[3];
    const float* vr     = (const float*)d_in[4];
    float* out = (float*)d_out;

    int G = in_sizes[1];
    int N = in_sizes[3] / 3;

    const int NX = 100, NY = 100, NZ = 8;
    if (N == NX * NY * NZ) {
        dim3 tiles((NX + TSX - 1) / TSX, (NY + TSY - 1) / TSY,
                   (NZ + TSZ - 1) / TSZ);
        gv_tile<<<tiles, 512>>>(means, ops, covs, vr, out, G, NX, NY, NZ);
    } else {
        gv_brute<<<(N + 255) / 256, 256>>>(means, ops, covs, coords, vr, out,
                                           G, N);
    }
}

// round 13
// speedup vs baseline: 1.4455x; 1.4455x over previous
#include <cuda_runtime.h>
#include <cuda_bf16.h>

// ---------------------------------------------------------------------------
// GaussianVoxelizer, single fused kernel (regular-grid path):
//   grid = 8x8x4-voxel tiles (13x13x2 = 338 blocks), 256 threads.
//   Thread mapping: quarter q = tid>>6 (warp-aligned), column c = tid&63.
//   Each thread owns one (x,y) column (4 z-voxels) and evals survivor
//   segments {2q, 2q+1}; the 2-D quadratic part is factored out per gaussian
//   (A + dz*(B + q22*dz)), so each extra z costs 2 FMA + ex2 + acc.
//   Combine: s_red[q][z*64+c], fixed-order 4-way sum (deterministic).
//   Cull: R9's proven 8-warp scan — hoisted full-MLP loads, exact 3-sigma
//   vol mask, 5-sigma per-axis tile cull, ballot compaction.
//   Cull safety: maha >= d_i^2/Sigma_ii => culled weight < exp(-12.5)~3.7e-6.
// Fallback (non-regular grid): brute force, correctness only.
// ---------------------------------------------------------------------------

#define GCHUNK 1024
#define SEG    (GCHUNK / 8)       // gaussians per cull-warp segment (128)
#define TSX 8
#define TSY 8
#define TSZ 4
#define CULL_K 5.0f

__device__ __forceinline__ float ex2_approx(float x) {
    float y;
    asm("ex2.approx.ftz.f32 %0, %1;" : "=f"(y) : "f"(x));
    return y;
}

__global__ __launch_bounds__(256) void gv_tile(
    const float* __restrict__ means,
    const float* __restrict__ ops,
    const float* __restrict__ covs,
    const float* __restrict__ vr,
    float* __restrict__ out,
    int G, int NX, int NY, int NZ) {
    __shared__ float4 s_a[GCHUNK];          // -mx, -my, -mz, op        (16 KB)
    __shared__ float4 s_b[GCHUNK];          // q00, 2q01, 2q02, q11     (16 KB)
    __shared__ float2 s_c[GCHUNK];          // 2q12, q22                 (8 KB)
    __shared__ float s_red[4][TSX * TSY * TSZ / 4 * 4];  // [q][z*64+c]  (4 KB)
    __shared__ int s_cnt[8];

    const int tid = threadIdx.x;
    const int lane = tid & 31;
    const int wid = tid >> 5;
    const int q = tid >> 6;        // survivor quarter (warp-aligned)
    const int c = tid & 63;        // xy column within tile

    const float v0 = vr[0], v1 = vr[1], v2 = vr[2];
    const float v3 = vr[3], v4 = vr[4], v5 = vr[5];
    const float voxx = (v3 - v0) / (float)NX;
    const float voxy = (v4 - v1) / (float)NY;
    const float voxz = (v5 - v2) / (float)NZ;

    // ---- analytic tile AABB (voxel centers, clamped) ----
    const int x0 = blockIdx.x * TSX, x1 = min(x0 + TSX - 1, NX - 1);
    const int y0 = blockIdx.y * TSY, y1 = min(y0 + TSY - 1, NY - 1);
    const int z0 = blockIdx.z * TSZ, z1 = min(z0 + TSZ - 1, NZ - 1);
    const float lox = v0 + ((float)x0 + 0.5f) * voxx;
    const float hix = v0 + ((float)x1 + 0.5f) * voxx;
    const float loy = v1 + ((float)y0 + 0.5f) * voxy;
    const float hiy = v1 + ((float)y1 + 0.5f) * voxy;
    const float loz = v2 + ((float)z0 + 0.5f) * voxz;
    const float hiz = v2 + ((float)z1 + 0.5f) * voxz;

    // ---- this thread's column (c: x = bits[3:6), y = bits[0:3)) ----
    const int X = x0 + (c >> 3);
    const int Y = y0 + (c & 7);
    const float cx = v0 + ((float)X + 0.5f) * voxx;
    const float cy = v1 + ((float)Y + 0.5f) * voxy;
    const float cz0 = v2 + ((float)z0 + 0.5f) * voxz;   // z of first voxel

    float acc0 = 0.f, acc1 = 0.f, acc2 = 0.f, acc3 = 0.f;

    for (int gbase = 0; gbase < G; gbase += GCHUNK) {
        const int chunk = min(GCHUNK, G - gbase);

        // ---- warp-private cull + compaction (8 warps, SEG=128) ----
        const int wbase = wid * SEG;
        int wcount = 0;
#pragma unroll
        for (int p = 0; p < SEG; p += 32) {
            const int rel = wbase + p + lane;
            const bool inb = rel < chunk;
            const int g = gbase + (inb ? rel : 0);

            // unconditional clamped loads -> full MLP batch
            float mx  = means[3 * g + 0];
            float my  = means[3 * g + 1];
            float mz  = means[3 * g + 2];
            float op  = ops[g];
            float caa = covs[9 * g + 0];
            float cab = covs[9 * g + 1];
            float cac = covs[9 * g + 2];
            float cbb = covs[9 * g + 4];
            float cbc = covs[9 * g + 5];
            float ccc = covs[9 * g + 8];

            float sqa = sqrtf(caa), sqb = sqrtf(cbb), sqc = sqrtf(ccc);
            // reference's 3-sigma volume-range mask (exact form)
            bool mask = (mx + 3.0f * sqa > v0) && (my + 3.0f * sqb > v1) &&
                        (mz + 3.0f * sqc > v2) && (mx - 3.0f * sqa < v3) &&
                        (my - 3.0f * sqb < v4) && (mz - 3.0f * sqc < v5);
            // 5-sigma per-axis tile cull
            float gx = fmaxf(fmaxf(lox - mx, mx - hix), 0.0f);
            float gy = fmaxf(fmaxf(loy - my, my - hiy), 0.0f);
            float gz = fmaxf(fmaxf(loz - mz, mz - hiz), 0.0f);
            bool survive = inb && mask && (op != 0.0f) &&
                           (gx <= CULL_K * sqa) && (gy <= CULL_K * sqb) &&
                           (gz <= CULL_K * sqc);

            // inversion hoisted (cheap math; wasted for dead lanes)
            float C00 = cbb * ccc - cbc * cbc;
            float C01 = cac * cbc - cab * ccc;
            float C02 = cab * cbc - cac * cbb;
            float C11 = caa * ccc - cac * cac;
            float C12 = cab * cac - caa * cbc;
            float C22 = caa * cbb - cab * cab;
            float det = caa * C00 + cab * C01 + cac * C02;
            float s = -0.72134752044448170f / det;

            unsigned m = __ballot_sync(0xffffffffu, survive);
            if (survive) {
                const int pos = wbase + wcount + __popc(m & ((1u << lane) - 1u));
                s_a[pos] = make_float4(-mx, -my, -mz, op);
                s_b[pos] = make_float4(s * C00, 2.0f * s * C01,
                                       2.0f * s * C02, s * C11);
                s_c[pos] = make_float2(2.0f * s * C12, s * C22);
            }
            wcount += __popc(m);
        }
        if (lane == 0) s_cnt[wid] = wcount;
        __syncthreads();

        // ---- eval: this quarter's 2 segments, full z-column per thread ----
#pragma unroll
        for (int s2 = 0; s2 < 2; ++s2) {
            const int w = q * 2 + s2;
            const int cw = s_cnt[w];
            const int sbase = w * SEG;
#pragma unroll 2
            for (int i = 0; i < cw; ++i) {
                float4 A = s_a[sbase + i];
                float4 B = s_b[sbase + i];
                float2 C = s_c[sbase + i];
                float dx = cx + A.x;
                float dy = cy + A.y;
                float dz = cz0 + A.z;
                // 2-D part, shared across the z-column
                float s1 = fmaf(B.y, dy, B.x * dx);          // q00 dx + 2q01 dy
                float A2 = fmaf(dx, s1, dy * (B.w * dy));    // + q11 dy^2
                float Bl = fmaf(C.x, dy, B.z * dx);          // 2q02 dx + 2q12 dy
                // per-z: ee = A2 + dz*(Bl + q22*dz)
                float u0 = fmaf(C.y, dz, Bl);
                float e0 = fmaf(dz, u0, A2);
                float dzb = dz + voxz;
                float u1 = fmaf(C.y, dzb, Bl);
                float e1 = fmaf(dzb, u1, A2);
                float dzc = dzb + voxz;
                float u2 = fmaf(C.y, dzc, Bl);
                float e2 = fmaf(dzc, u2, A2);
                float dzd = dzc + voxz;
                float u3 = fmaf(C.y, dzd, Bl);
                float e3 = fmaf(dzd, u3, A2);
                acc0 = fmaf(A.w, ex2_approx(e0), acc0);
                acc1 = fmaf(A.w, ex2_approx(e1), acc1);
                acc2 = fmaf(A.w, ex2_approx(e2), acc2);
                acc3 = fmaf(A.w, ex2_approx(e3), acc3);
            }
        }
        __syncthreads();
    }

    // ---- combine quarters, fixed order (deterministic) ----
    s_red[q][0 * 64 + c] = acc0;
    s_red[q][1 * 64 + c] = acc1;
    s_red[q][2 * 64 + c] = acc2;
    s_red[q][3 * 64 + c] = acc3;
    __syncthreads();
    {
        const int rz = tid >> 6;    // z within tile
        const int rc = tid & 63;    // column
        const int RX = x0 + (rc >> 3);
        const int RY = y0 + (rc & 7);
        const int RZ = z0 + rz;
        if (RX < NX && RY < NY && RZ < NZ) {
            const int idx = rz * 64 + rc;
            float sum = ((s_red[0][idx] + s_red[1][idx]) + s_red[2][idx]) +
                        s_red[3][idx];
            out[(RX * NY + RY) * NZ + RZ] = sum;
        }
    }
}

// Generic fallback: brute force over all gaussians per voxel (any layout).
__global__ __launch_bounds__(256) void gv_brute(
    const float* __restrict__ means,
    const float* __restrict__ ops,
    const float* __restrict__ covs,
    const float* __restrict__ coords,
    const float* __restrict__ vr,
    float* __restrict__ out,
    int G, int N) {
    __shared__ float4 s_a[GCHUNK];
    __shared__ float4 s_b[GCHUNK];
    __shared__ float2 s_c[GCHUNK];
    const int tid = threadIdx.x;
    const float v0 = vr[0], v1 = vr[1], v2 = vr[2];
    const float v3 = vr[3], v4 = vr[4], v5 = vr[5];
    int vidx = blockIdx.x * 256 + tid;
    bool valid = vidx < N;
    int li = valid ? vidx : 0;
    float cx = coords[3 * li + 0];
    float cy = coords[3 * li + 1];
    float cz = coords[3 * li + 2];
    float acc = 0.0f;
    for (int base = 0; base < G; base += GCHUNK) {
        int c = min(GCHUNK, G - base);
        for (int i = tid; i < c; i += 256) {
            int g = base + i;
            float mx = means[3 * g + 0];
            float my = means[3 * g + 1];
            float mz = means[3 * g + 2];
            float op = ops[g];
            float caa = covs[9 * g + 0];
            float cab = covs[9 * g + 1];
            float cac = covs[9 * g + 2];
            float cbb = covs[9 * g + 4];
            float cbc = covs[9 * g + 5];
            float ccc = covs[9 * g + 8];
            float sqa = sqrtf(caa), sqb = sqrtf(cbb), sqc = sqrtf(ccc);
            bool mask = (mx + 3.0f * sqa > v0) && (my + 3.0f * sqb > v1) &&
                        (mz + 3.0f * sqc > v2) && (mx - 3.0f * sqa < v3) &&
                        (my - 3.0f * sqb < v4) && (mz - 3.0f * sqc < v5);
            if (!mask) op = 0.0f;
            float C00 = cbb * ccc - cbc * cbc;
            float C01 = cac * cbc - cab * ccc;
            float C02 = cab * cbc - cac * cbb;
            float C11 = caa * ccc - cac * cac;
            float C12 = cab * cac - caa * cbc;
            float C22 = caa * cbb - cab * cab;
            float det = caa * C00 + cab * C01 + cac * C02;
            float s = -0.72134752044448170f / det;
            s_a[i] = make_float4(-mx, -my, -mz, op);
            s_b[i] = make_float4(s * C00, 2.0f * s * C01, 2.0f * s * C02,
                                 s * C11);
            s_c[i] = make_float2(2.0f * s * C12, s * C22);
        }
        __syncthreads();
        for (int i = 0; i < c; ++i) {
            float4 A = s_a[i];
            float4 B = s_b[i];
            float2 C = s_c[i];
            float dx = cx + A.x;
            float dy = cy + A.y;
            float dz = cz + A.z;
            float t0 = fmaf(B.x, dx, fmaf(B.y, dy, B.z * dz));
            float t1 = fmaf(B.w, dy, C.x * dz);
            float ee = fmaf(dx, t0, fmaf(dy, t1, (C.y * dz) * dz));
            acc = fmaf(A.w, ex2_approx(ee), acc);
        }
        __syncthreads();
    }
    if (valid) out[vidx] = acc;
}

extern "C" void kernel_launch(void* const* d_in, const int* in_sizes, int n_in,
                              void* d_out, int out_size) {
    const float* means  = (const float*)d_in[0];
    const float* ops    = (const float*)d_in[1];
    const float* covs   = (const float*)d_in[2];
    const float* coords = (const float*)d_in[3];
    const float* vr     = (const float*)d_in[4];
    float* out = (float*)d_out;

    int G = in_sizes[1];
    int N = in_sizes[3] / 3;

    const int NX = 100, NY = 100, NZ = 8;
    if (N == NX * NY * NZ) {
        dim3 tiles((NX + TSX - 1) / TSX, (NY + TSY - 1) / TSY,
                   (NZ + TSZ - 1) / TSZ);
        gv_tile<<<tiles, 256>>>(means, ops, covs, vr, out, G, NX, NY, NZ);
    } else {
        gv_brute<<<(N + 255) / 256, 256>>>(means, ops, covs, coords, vr, out,
                                           G, N);
    }
}

// round 14
// speedup vs baseline: 1.6111x; 1.1146x over previous
#include <cuda_runtime.h>
#include <cuda_bf16.h>

// ---------------------------------------------------------------------------
// GaussianVoxelizer, single fused kernel (regular-grid path):
//   grid = 8x8x8-voxel tiles (13x13 = 169 blocks), 512 threads.
//   Eighth e = tid>>6 (warp-aligned pairs), column c = tid&63 (8x8 xy).
//   Each thread owns one (x,y) column (ALL 8 z-voxels) and evals survivor
//   segments {2e, 2e+1}; 2-D quadratic part factored per gaussian
//   (ee = A2 + dz*(Bl + q22*dz)) with 8 independent z-accumulators.
//   Cull: 16 warps, SEG=64 (2 passes/warp), hoisted full-MLP loads,
//   sqrt-free squared-form tests (exact 3-sigma vol mask + 5-sigma tile cull),
//   ballot compaction.  Combine: s_a-aliased buffer, fixed-order 8-way sum.
//   Cull safety: maha >= d_i^2/Sigma_ii => culled weight < exp(-12.5)~3.7e-6.
// Fallback (non-regular grid): brute force, correctness only.
// ---------------------------------------------------------------------------

#define GCHUNK 1024
#define NWARP  16
#define SEG    (GCHUNK / NWARP)   // 64 gaussians per cull-warp segment
#define TSX 8
#define TSY 8
#define TSZ 8
#define CULL_K2 25.0f             // (5 sigma)^2

__device__ __forceinline__ float ex2_approx(float x) {
    float y;
    asm("ex2.approx.ftz.f32 %0, %1;" : "=f"(y) : "f"(x));
    return y;
}

__global__ __launch_bounds__(512, 2) void gv_tile(
    const float* __restrict__ means,
    const float* __restrict__ ops,
    const float* __restrict__ covs,
    const float* __restrict__ vr,
    float* __restrict__ out,
    int G, int NX, int NY, int NZ) {
    __shared__ float4 s_a[GCHUNK];          // -mx, -my, -mz, op        (16 KB)
    __shared__ float4 s_b[GCHUNK];          // q00, 2q01, 2q02, q11     (16 KB)
    __shared__ float2 s_c[GCHUNK];          // 2q12, q22                 (8 KB)
    __shared__ int s_cnt[NWARP];

    const int tid = threadIdx.x;
    const int lane = tid & 31;
    const int wid = tid >> 5;
    const int e = tid >> 6;        // survivor eighth (2 segments)
    const int c = tid & 63;        // xy column within tile

    const float v0 = vr[0], v1 = vr[1], v2 = vr[2];
    const float v3 = vr[3], v4 = vr[4], v5 = vr[5];
    const float voxx = (v3 - v0) / (float)NX;
    const float voxy = (v4 - v1) / (float)NY;
    const float voxz = (v5 - v2) / (float)NZ;

    // ---- analytic tile AABB (voxel centers, clamped) ----
    const int x0 = blockIdx.x * TSX, x1 = min(x0 + TSX - 1, NX - 1);
    const int y0 = blockIdx.y * TSY, y1 = min(y0 + TSY - 1, NY - 1);
    const int z0 = blockIdx.z * TSZ, z1 = min(z0 + TSZ - 1, NZ - 1);
    const float lox = v0 + ((float)x0 + 0.5f) * voxx;
    const float hix = v0 + ((float)x1 + 0.5f) * voxx;
    const float loy = v1 + ((float)y0 + 0.5f) * voxy;
    const float hiy = v1 + ((float)y1 + 0.5f) * voxy;
    const float loz = v2 + ((float)z0 + 0.5f) * voxz;
    const float hiz = v2 + ((float)z1 + 0.5f) * voxz;

    // ---- this thread's column (c: x = bits[3:6), y = bits[0:3)) ----
    const int X = x0 + (c >> 3);
    const int Y = y0 + (c & 7);
    const float cx = v0 + ((float)X + 0.5f) * voxx;
    const float cy = v1 + ((float)Y + 0.5f) * voxy;
    const float cz0 = v2 + ((float)z0 + 0.5f) * voxz;   // z of first voxel

    float acc[TSZ];
#pragma unroll
    for (int z = 0; z < TSZ; ++z) acc[z] = 0.0f;

    for (int gbase = 0; gbase < G; gbase += GCHUNK) {
        const int chunk = min(GCHUNK, G - gbase);

        // ---- warp-private cull + compaction (16 warps, SEG=64, 2 passes) ----
        const int wbase = wid * SEG;
        int wcount = 0;
#pragma unroll
        for (int p = 0; p < SEG; p += 32) {
            const int rel = wbase + p + lane;
            const bool inb = rel < chunk;
            const int g = gbase + (inb ? rel : 0);

            // unconditional clamped loads -> full MLP batch
            float mx  = means[3 * g + 0];
            float my  = means[3 * g + 1];
            float mz  = means[3 * g + 2];
            float op  = ops[g];
            float caa = covs[9 * g + 0];
            float cab = covs[9 * g + 1];
            float cac = covs[9 * g + 2];
            float cbb = covs[9 * g + 4];
            float cbc = covs[9 * g + 5];
            float ccc = covs[9 * g + 8];

            // reference's 3-sigma vol mask, squared form:
            //   m + 3s > v  <=>  (v-m) < 0 || 9c > (v-m)^2
            float a0 = v0 - mx, a3 = mx - v3;
            float b1 = v1 - my, b4 = my - v4;
            float c2 = v2 - mz, c5 = mz - v5;
            bool mok = ((a0 < 0.f) | (9.f * caa > a0 * a0)) &
                       ((a3 < 0.f) | (9.f * caa > a3 * a3)) &
                       ((b1 < 0.f) | (9.f * cbb > b1 * b1)) &
                       ((b4 < 0.f) | (9.f * cbb > b4 * b4)) &
                       ((c2 < 0.f) | (9.f * ccc > c2 * c2)) &
                       ((c5 < 0.f) | (9.f * ccc > c5 * c5));
            // 5-sigma per-axis tile cull, squared form
            float gx = fmaxf(fmaxf(lox - mx, mx - hix), 0.0f);
            float gy = fmaxf(fmaxf(loy - my, my - hiy), 0.0f);
            float gz = fmaxf(fmaxf(loz - mz, mz - hiz), 0.0f);
            bool survive = inb && mok && (op != 0.0f) &&
                           (gx * gx <= CULL_K2 * caa) &&
                           (gy * gy <= CULL_K2 * cbb) &&
                           (gz * gz <= CULL_K2 * ccc);

            // inversion hoisted (cheap math; wasted for dead lanes)
            float C00 = cbb * ccc - cbc * cbc;
            float C01 = cac * cbc - cab * ccc;
            float C02 = cab * cbc - cac * cbb;
            float C11 = caa * ccc - cac * cac;
            float C12 = cab * cac - caa * cbc;
            float C22 = caa * cbb - cab * cab;
            float det = caa * C00 + cab * C01 + cac * C02;
            float s = -0.72134752044448170f / det;

            unsigned m = __ballot_sync(0xffffffffu, survive);
            if (survive) {
                const int pos = wbase + wcount + __popc(m & ((1u << lane) - 1u));
                s_a[pos] = make_float4(-mx, -my, -mz, op);
                s_b[pos] = make_float4(s * C00, 2.0f * s * C01,
                                       2.0f * s * C02, s * C11);
                s_c[pos] = make_float2(2.0f * s * C12, s * C22);
            }
            wcount += __popc(m);
        }
        if (lane == 0) s_cnt[wid] = wcount;
        __syncthreads();

        // ---- eval: this eighth's 2 segments, full 8-z column per thread ----
#pragma unroll
        for (int s2 = 0; s2 < 2; ++s2) {
            const int w = e * 2 + s2;
            const int cw = s_cnt[w];
            const int sbase = w * SEG;
            for (int i = 0; i < cw; ++i) {
                float4 A = s_a[sbase + i];
                float4 B = s_b[sbase + i];
                float2 C = s_c[sbase + i];
                float dx = cx + A.x;
                float dy = cy + A.y;
                float dzb = cz0 + A.z;
                // 2-D part, shared across the z-column
                float s1 = fmaf(B.y, dy, B.x * dx);          // q00 dx + 2q01 dy
                float A2 = fmaf(dx, s1, dy * (B.w * dy));    // + q11 dy^2
                float Bl = fmaf(C.x, dy, B.z * dx);          // 2q02 dx + 2q12 dy
#pragma unroll
                for (int z = 0; z < TSZ; ++z) {
                    float dzk = fmaf((float)z, voxz, dzb);   // independent FMAs
                    float u = fmaf(C.y, dzk, Bl);
                    float ee = fmaf(dzk, u, A2);
                    acc[z] = fmaf(A.w, ex2_approx(ee), acc[z]);
                }
            }
        }
        __syncthreads();
    }

    // ---- combine eighths via s_a alias, fixed order (deterministic) ----
    float* s_red = (float*)s_a;   // records dead after last eval sync
#pragma unroll
    for (int z = 0; z < TSZ; ++z) s_red[e * 512 + z * 64 + c] = acc[z];
    __syncthreads();
    {
        const int rz = tid >> 6;    // z within tile
        const int rc = tid & 63;    // column
        const int RX = x0 + (rc >> 3);
        const int RY = y0 + (rc & 7);
        const int RZ = z0 + rz;
        if (RX < NX && RY < NY && RZ < NZ) {
            const int idx = rz * 64 + rc;
            float sum = s_red[idx];
#pragma unroll
            for (int ee8 = 1; ee8 < 8; ++ee8) sum += s_red[ee8 * 512 + idx];
            out[(RX * NY + RY) * NZ + RZ] = sum;
        }
    }
}

// Generic fallback: brute force over all gaussians per voxel (any layout).
__global__ __launch_bounds__(256) void gv_brute(
    const float* __restrict__ means,
    const float* __restrict__ ops,
    const float* __restrict__ covs,
    const float* __restrict__ coords,
    const float* __restrict__ vr,
    float* __restrict__ out,
    int G, int N) {
    __shared__ float4 s_a[GCHUNK];
    __shared__ float4 s_b[GCHUNK];
    __shared__ float2 s_c[GCHUNK];
    const int tid = threadIdx.x;
    const float v0 = vr[0], v1 = vr[1], v2 = vr[2];
    const float v3 = vr[3], v4 = vr[4], v5 = vr[5];
    int vidx = blockIdx.x * 256 + tid;
    bool valid = vidx < N;
    int li = valid ? vidx : 0;
    float cx = coords[3 * li + 0];
    float cy = coords[3 * li + 1];
    float cz = coords[3 * li + 2];
    float acc = 0.0f;
    for (int base = 0; base < G; base += GCHUNK) {
        int c = min(GCHUNK, G - base);
        for (int i = tid; i < c; i += 256) {
            int g = base + i;
            float mx = means[3 * g + 0];
            float my = means[3 * g + 1];
            float mz = means[3 * g + 2];
            float op = ops[g];
            float caa = covs[9 * g + 0];
            float cab = covs[9 * g + 1];
            float cac = covs[9 * g + 2];
            float cbb = covs[9 * g + 4];
            float cbc = covs[9 * g + 5];
            float ccc = covs[9 * g + 8];
            float sqa = sqrtf(caa), sqb = sqrtf(cbb), sqc = sqrtf(ccc);
            bool mask = (mx + 3.0f * sqa > v0) && (my + 3.0f * sqb > v1) &&
                        (mz + 3.0f * sqc > v2) && (mx - 3.0f * sqa < v3) &&
                        (my - 3.0f * sqb < v4) && (mz - 3.0f * sqc < v5);
            if (!mask) op = 0.0f;
            float C00 = cbb * ccc - cbc * cbc;
            float C01 = cac * cbc - cab * ccc;
            float C02 = cab * cbc - cac * cbb;
            float C11 = caa * ccc - cac * cac;
            float C12 = cab * cac - caa * cbc;
            float C22 = caa * cbb - cab * cab;
            float det = caa * C00 + cab * C01 + cac * C02;
            float s = -0.72134752044448170f / det;
            s_a[i] = make_float4(-mx, -my, -mz, op);
            s_b[i] = make_float4(s * C00, 2.0f * s * C01, 2.0f * s * C02,
                                 s * C11);
            s_c[i] = make_float2(2.0f * s * C12, s * C22);
        }
        __syncthreads();
        for (int i = 0; i < c; ++i) {
            float4 A = s_a[i];
            float4 B = s_b[i];
            float2 C = s_c[i];
            float dx = cx + A.x;
            float dy = cy + A.y;
            float dz = cz + A.z;
            float t0 = fmaf(B.x, dx, fmaf(B.y, dy, B.z * dz));
            float t1 = fmaf(B.w, dy, C.x * dz);
            float ee = fmaf(dx, t0, fmaf(dy, t1, (C.y * dz) * dz));
            acc = fmaf(A.w, ex2_approx(ee), acc);
        }
        __syncthreads();
    }
    if (valid) out[vidx] = acc;
}

extern "C" void kernel_launch(void* const* d_in, const int* in_sizes, int n_in,
                              void* d_out, int out_size) {
    const float* means  = (const float*)d_in[0];
    const float* ops    = (const float*)d_in[1];
    const float* covs   = (const float*)d_in[2];
    const float* coords = (const float*)d_in[3];
    const float* vr     = (const float*)d_in[4];
    float* out = (float*)d_out;

    int G = in_sizes[1];
    int N = in_sizes[3] / 3;

    const int NX = 100, NY = 100, NZ = 8;
    if (N == NX * NY * NZ) {
        dim3 tiles((NX + TSX - 1) / TSX, (NY + TSY - 1) / TSY,
                   (NZ + TSZ - 1) / TSZ);
        gv_tile<<<tiles, 512>>>(means, ops, covs, vr, out, G, NX, NY, NZ);
    } else {
        gv_brute<<<(N + 255) / 256, 256>>>(means, ops, covs, coords, vr, out,
                                           G, N);
    }
}

// round 16
// speedup vs baseline: 1.6338x; 1.0141x over previous
#include <cuda_runtime.h>
#include <cuda_bf16.h>

// ---------------------------------------------------------------------------
// GaussianVoxelizer, single fused kernel (regular-grid path):
//   grid = 10x8x8-voxel tiles (10x13 = 130 blocks <= 148 SMs: single wave,
//   no second-block tail), 512 threads, __launch_bounds__(512,1) so regs
//   (~<=128) can fund an unroll-2 pipelined eval loop.
//   Mapping: group g = tid/80 (6 eval groups; last 32 threads idle in eval),
//   column c = tid%80 (10x8 xy). Each thread owns one column (all 8 z) and
//   evals survivor segments {g, g+6, g+12}; 2-D quadratic part factored per
//   gaussian (ee = A2 + dz*(Bl + q22*dz)), 8 independent z-accumulators,
//   2 gaussians in flight per iteration.
//   Cull: 16 warps, SEG=64, hoisted full-MLP loads, sqrt-free squared-form
//   tests (exact 3-sigma vol mask + 5-sigma tile cull), ballot compaction.
//   Combine: s_a-aliased buffer (6*640 floats), fixed order (deterministic).
//   Cull safety: maha >= d_i^2/Sigma_ii => culled weight < exp(-12.5)~3.7e-6.
// Fallback (non-regular grid): brute force, correctness only.
// ---------------------------------------------------------------------------

#define GCHUNK 1024
#define NWARP  16
#define SEG    (GCHUNK / NWARP)   // 64 gaussians per cull-warp segment
#define TSX 10
#define TSY 8
#define TSZ 8
#define NCOL (TSX * TSY)          // 80 columns
#define NGRP 6
#define CULL_K2 25.0f             // (5 sigma)^2

__device__ __forceinline__ float ex2_approx(float x) {
    float y;
    asm("ex2.approx.ftz.f32 %0, %1;" : "=f"(y) : "f"(x));
    return y;
}

// Factored column eval: one gaussian, all TSZ z's of this thread's column.
__device__ __forceinline__ void eval_col(
    const float4 A, const float4 B, const float2 C,
    float cx, float cy, float cz0, float voxz, float (&acc)[TSZ]) {
    float dx = cx + A.x;
    float dy = cy + A.y;
    float dzb = cz0 + A.z;
    float s1 = fmaf(B.y, dy, B.x * dx);          // q00 dx + 2q01 dy
    float A2 = fmaf(dx, s1, dy * (B.w * dy));    // + q11 dy^2
    float Bl = fmaf(C.x, dy, B.z * dx);          // 2q02 dx + 2q12 dy
#pragma unroll
    for (int z = 0; z < TSZ; ++z) {
        float dzk = fmaf((float)z, voxz, dzb);
        float u = fmaf(C.y, dzk, Bl);
        float ee = fmaf(dzk, u, A2);
        acc[z] = fmaf(A.w, ex2_approx(ee), acc[z]);
    }
}

__global__ __launch_bounds__(512, 1) void gv_tile(
    const float* __restrict__ means,
    const float* __restrict__ ops,
    const float* __restrict__ covs,
    const float* __restrict__ vr,
    float* __restrict__ out,
    int G, int NX, int NY, int NZ) {
    __shared__ float4 s_a[GCHUNK];          // -mx, -my, -mz, op        (16 KB)
    __shared__ float4 s_b[GCHUNK];          // q00, 2q01, 2q02, q11     (16 KB)
    __shared__ float2 s_c[GCHUNK];          // 2q12, q22                 (8 KB)
    __shared__ int s_cnt[NWARP];

    const int tid = threadIdx.x;
    const int lane = tid & 31;
    const int wid = tid >> 5;
    const int g8 = tid / NCOL;     // eval group (0..5 active, 6 idle)
    const int c = tid - g8 * NCOL; // xy column within tile

    const float v0 = vr[0], v1 = vr[1], v2 = vr[2];
    const float v3 = vr[3], v4 = vr[4], v5 = vr[5];
    const float voxx = (v3 - v0) / (float)NX;
    const float voxy = (v4 - v1) / (float)NY;
    const float voxz = (v5 - v2) / (float)NZ;

    // ---- analytic tile AABB (voxel centers, clamped) ----
    const int x0 = blockIdx.x * TSX, x1 = min(x0 + TSX - 1, NX - 1);
    const int y0 = blockIdx.y * TSY, y1 = min(y0 + TSY - 1, NY - 1);
    const int z0 = blockIdx.z * TSZ, z1 = min(z0 + TSZ - 1, NZ - 1);
    const float lox = v0 + ((float)x0 + 0.5f) * voxx;
    const float hix = v0 + ((float)x1 + 0.5f) * voxx;
    const float loy = v1 + ((float)y0 + 0.5f) * voxy;
    const float hiy = v1 + ((float)y1 + 0.5f) * voxy;
    const float loz = v2 + ((float)z0 + 0.5f) * voxz;
    const float hiz = v2 + ((float)z1 + 0.5f) * voxz;

    // ---- this thread's column (c: x = c/TSY, y = c%TSY) ----
    const int X = x0 + c / TSY;
    const int Y = y0 + (c % TSY);
    const float cx = v0 + ((float)X + 0.5f) * voxx;
    const float cy = v1 + ((float)Y + 0.5f) * voxy;
    const float cz0 = v2 + ((float)z0 + 0.5f) * voxz;

    float acc[TSZ];
#pragma unroll
    for (int z = 0; z < TSZ; ++z) acc[z] = 0.0f;

    for (int gbase = 0; gbase < G; gbase += GCHUNK) {
        const int chunk = min(GCHUNK, G - gbase);

        // ---- warp-private cull + compaction (16 warps, SEG=64) ----
        const int wbase = wid * SEG;
        int wcount = 0;
#pragma unroll
        for (int p = 0; p < SEG; p += 32) {
            const int rel = wbase + p + lane;
            const bool inb = rel < chunk;
            const int gg = gbase + (inb ? rel : 0);

            // unconditional clamped loads -> full MLP batch
            float mx  = means[3 * gg + 0];
            float my  = means[3 * gg + 1];
            float mz  = means[3 * gg + 2];
            float op  = ops[gg];
            float caa = covs[9 * gg + 0];
            float cab = covs[9 * gg + 1];
            float cac = covs[9 * gg + 2];
            float cbb = covs[9 * gg + 4];
            float cbc = covs[9 * gg + 5];
            float ccc = covs[9 * gg + 8];

            // reference's 3-sigma vol mask, squared form
            float a0 = v0 - mx, a3 = mx - v3;
            float b1 = v1 - my, b4 = my - v4;
            float c2 = v2 - mz, c5 = mz - v5;
            bool mok = ((a0 < 0.f) | (9.f * caa > a0 * a0)) &
                       ((a3 < 0.f) | (9.f * caa > a3 * a3)) &
                       ((b1 < 0.f) | (9.f * cbb > b1 * b1)) &
                       ((b4 < 0.f) | (9.f * cbb > b4 * b4)) &
                       ((c2 < 0.f) | (9.f * ccc > c2 * c2)) &
                       ((c5 < 0.f) | (9.f * ccc > c5 * c5));
            // 5-sigma per-axis tile cull, squared form
            float gx = fmaxf(fmaxf(lox - mx, mx - hix), 0.0f);
            float gy = fmaxf(fmaxf(loy - my, my - hiy), 0.0f);
            float gz = fmaxf(fmaxf(loz - mz, mz - hiz), 0.0f);
            bool survive = inb && mok && (op != 0.0f) &&
                           (gx * gx <= CULL_K2 * caa) &&
                           (gy * gy <= CULL_K2 * cbb) &&
                           (gz * gz <= CULL_K2 * ccc);

            // inversion hoisted
            float C00 = cbb * ccc - cbc * cbc;
            float C01 = cac * cbc - cab * ccc;
            float C02 = cab * cbc - cac * cbb;
            float C11 = caa * ccc - cac * cac;
            float C12 = cab * cac - caa * cbc;
            float C22 = caa * cbb - cab * cab;
            float det = caa * C00 + cab * C01 + cac * C02;
            float s = -0.72134752044448170f / det;

            unsigned m = __ballot_sync(0xffffffffu, survive);
            if (survive) {
                const int pos = wbase + wcount + __popc(m & ((1u << lane) - 1u));
                s_a[pos] = make_float4(-mx, -my, -mz, op);
                s_b[pos] = make_float4(s * C00, 2.0f * s * C01,
                                       2.0f * s * C02, s * C11);
                s_c[pos] = make_float2(2.0f * s * C12, s * C22);
            }
            wcount += __popc(m);
        }
        if (lane == 0) s_cnt[wid] = wcount;
        __syncthreads();

        // ---- eval: group's segments {g8, g8+6, g8+12}, unroll-2 pipeline ----
        if (g8 < NGRP) {
            for (int s = g8; s < NWARP; s += NGRP) {
                const int cw = s_cnt[s];
                const int sb = s * SEG;
                int i = 0;
                for (; i + 2 <= cw; i += 2) {
                    float4 A0 = s_a[sb + i],     B0 = s_b[sb + i];
                    float2 C0 = s_c[sb + i];
                    float4 A1 = s_a[sb + i + 1], B1 = s_b[sb + i + 1];
                    float2 C1 = s_c[sb + i + 1];
                    eval_col(A0, B0, C0, cx, cy, cz0, voxz, acc);
                    eval_col(A1, B1, C1, cx, cy, cz0, voxz, acc);
                }
                if (i < cw)
                    eval_col(s_a[sb + i], s_b[sb + i], s_c[sb + i],
                             cx, cy, cz0, voxz, acc);
            }
        }
        __syncthreads();
    }

    // ---- combine groups via s_a alias, fixed order (deterministic) ----
    float* s_red = (float*)s_a;   // 4096 floats; we use 6*640 = 3840
    if (g8 < NGRP) {
#pragma unroll
        for (int z = 0; z < TSZ; ++z)
            s_red[g8 * (NCOL * TSZ) + z * NCOL + c] = acc[z];
    }
    __syncthreads();
    for (int v = tid; v < NCOL * TSZ; v += 512) {
        const int rz = v / NCOL;
        const int rc = v - rz * NCOL;
        const int RX = x0 + rc / TSY;
        const int RY = y0 + (rc % TSY);
        const int RZ = z0 + rz;
        if (RX < NX && RY < NY && RZ < NZ) {
            float sum = s_red[v];
#pragma unroll
            for (int gg6 = 1; gg6 < NGRP; ++gg6)
                sum += s_red[gg6 * (NCOL * TSZ) + v];
            out[(RX * NY + RY) * NZ + RZ] = sum;
        }
    }
}

// Generic fallback: brute force over all gaussians per voxel (any layout).
__global__ __launch_bounds__(256) void gv_brute(
    const float* __restrict__ means,
    const float* __restrict__ ops,
    const float* __restrict__ covs,
    const float* __restrict__ coords,
    const float* __restrict__ vr,
    float* __restrict__ out,
    int G, int N) {
    __shared__ float4 s_a[GCHUNK];
    __shared__ float4 s_b[GCHUNK];
    __shared__ float2 s_c[GCHUNK];
    const int tid = threadIdx.x;
    const float v0 = vr[0], v1 = vr[1], v2 = vr[2];
    const float v3 = vr[3], v4 = vr[4], v5 = vr[5];
    int vidx = blockIdx.x * 256 + tid;
    bool valid = vidx < N;
    int li = valid ? vidx : 0;
    float cx = coords[3 * li + 0];
    float cy = coords[3 * li + 1];
    float cz = coords[3 * li + 2];
    float acc = 0.0f;
    for (int base = 0; base < G; base += GCHUNK) {
        int c = min(GCHUNK, G - base);
        for (int i = tid; i < c; i += 256) {
            int g = base + i;
            float mx = means[3 * g + 0];
            float my = means[3 * g + 1];
            float mz = means[3 * g + 2];
            float op = ops[g];
            float caa = covs[9 * g + 0];
            float cab = covs[9 * g + 1];
            float cac = covs[9 * g + 2];
            float cbb = covs[9 * g + 4];
            float cbc = covs[9 * g + 5];
            float ccc = covs[9 * g + 8];
            float sqa = sqrtf(caa), sqb = sqrtf(cbb), sqc = sqrtf(ccc);
            bool mask = (mx + 3.0f * sqa > v0) && (my + 3.0f * sqb > v1) &&
                        (mz + 3.0f * sqc > v2) && (mx - 3.0f * sqa < v3) &&
                        (my - 3.0f * sqb < v4) && (mz - 3.0f * sqc < v5);
            if (!mask) op = 0.0f;
            float C00 = cbb * ccc - cbc * cbc;
            float C01 = cac * cbc - cab * ccc;
            float C02 = cab * cbc - cac * cbb;
            float C11 = caa * ccc - cac * cac;
            float C12 = cab * cac - caa * cbc;
            float C22 = caa * cbb - cab * cab;
            float det = caa * C00 + cab * C01 + cac * C02;
            float s = -0.72134752044448170f / det;
            s_a[i] = make_float4(-mx, -my, -mz, op);
            s_b[i] = make_float4(s * C00, 2.0f * s * C01, 2.0f * s * C02,
                                 s * C11);
            s_c[i] = make_float2(2.0f * s * C12, s * C22);
        }
        __syncthreads();
        for (int i = 0; i < c; ++i) {
            float4 A = s_a[i];
            float4 B = s_b[i];
            float2 C = s_c[i];
            float dx = cx + A.x;
            float dy = cy + A.y;
            float dz = cz + A.z;
            float t0 = fmaf(B.x, dx, fmaf(B.y, dy, B.z * dz));
            float t1 = fmaf(B.w, dy, C.x * dz);
            float ee = fmaf(dx, t0, fmaf(dy, t1, (C.y * dz) * dz));
            acc = fmaf(A.w, ex2_approx(ee), acc);
        }
        __syncthreads();
    }
    if (valid) out[vidx] = acc;
}

extern "C" void kernel_launch(void* const* d_in, const int* in_sizes, int n_in,
                              void* d_out, int out_size) {
    const float* means  = (const float*)d_in[0];
    const float* ops    = (const float*)d_in[1];
    const float* covs   = (const float*)d_in[2];
    const float* coords = (const float*)d_in[3];
    const float* vr     = (const float*)d_in[4];
    float* out = (float*)d_out;

    int G = in_sizes[1];
    int N = in_sizes[3] / 3;

    const int NX = 100, NY = 100, NZ = 8;
    if (N == NX * NY * NZ) {
        dim3 tiles((NX + TSX - 1) / TSX, (NY + TSY - 1) / TSY,
                   (NZ + TSZ - 1) / TSZ);
        gv_tile<<<tiles, 512>>>(means, ops, covs, vr, out, G, NX, NY, NZ);
    } else {
        gv_brute<<<(N + 255) / 256, 256>>>(means, ops, covs, coords, vr, out,
                                           G, N);
    }
}